// round 5
// baseline (speedup 1.0000x reference)
#include <cuda_runtime.h>
#include <math.h>

#define BB 8
#define HH 384
#define WW 384
#define CC 3
#define NPAR 6
#define DELTA 10
#define LAM 0.05f
#define TOLF 1e-3f
#define MAXIT 12

#define PIX (HH*WW)
#define VW (WW - 2*DELTA)   // 364
#define VH (HH - 2*DELTA)   // 364

// k_iter: block = 128x2 threads, each block covers 4 rows (2 rows per y-slice * 2 slices)
#define TBX 128
#define TBY 2
#define ROWS1 4
#define NBLK1 (VH/ROWS1)    // 91
#define ROWSF 4
#define NBLKF (HH/ROWSF)    // 96

// Output layout: pf[B*6] | err[B] | DI[B*H*W*C] | Iw[B*H*W*C]
#define OUT_P   0
#define OUT_ERR (BB*NPAR)                 // 48
#define OUT_DI  (BB*NPAR + BB)            // 56
#define OUT_IW  (OUT_DI + BB*PIX*CC)      // 56 + 3538944

// -------- scratch (no runtime allocation allowed) --------
__device__ float g_I1p[BB*CC*PIX];   // planar I1
__device__ float g_I2p[BB*CC*PIX];   // planar I2
__device__ float g_p[BB*NPAR];
__device__ int   g_done[BB];
__device__ float g_part[BB*NBLK1*27];
__device__ float g_fpart[BB*NBLKF*2];

// -------- helpers --------
__device__ __forceinline__ float cubw(float s) {
    // a = -0.5 Keys cubic, matching reference piecewise definition
    s = fabsf(s);
    float s2 = s*s, s3 = s2*s;
    float w1 = 1.5f*s3 - 2.5f*s2 + 1.0f;
    float w2 = -0.5f*s3 + 2.5f*s2 - 4.0f*s + 2.0f;
    return (s <= 1.0f) ? w1 : ((s < 2.0f) ? w2 : 0.0f);
}

__device__ __forceinline__ void bicubic3(const float* __restrict__ I2b,
                                         float xg, float yg, float out[3]) {
    float x0 = floorf(xg), y0 = floorf(yg);
    float tx = xg - x0, ty = yg - y0;
    int xi = (int)x0, yi = (int)y0;
    float wx[4], wy[4];
    int xx[4], yy[4];
#pragma unroll
    for (int k = 0; k < 4; k++) {
        wx[k] = cubw(tx - (float)(k - 1));
        wy[k] = cubw(ty - (float)(k - 1));
        int xc = xi + k - 1; xc = xc < 0 ? 0 : (xc > WW-1 ? WW-1 : xc);
        int yc = yi + k - 1; yc = yc < 0 ? 0 : (yc > HH-1 ? HH-1 : yc);
        xx[k] = xc; yy[k] = yc;
    }
#pragma unroll
    for (int c = 0; c < CC; c++) {
        const float* pc = I2b + c*PIX;
        float acc = 0.0f;
#pragma unroll
        for (int j = 0; j < 4; j++) {
            const float* pr = pc + yy[j]*WW;
            float r = wx[0]*__ldg(pr+xx[0]) + wx[1]*__ldg(pr+xx[1])
                    + wx[2]*__ldg(pr+xx[2]) + wx[3]*__ldg(pr+xx[3]);
            acc = fmaf(wy[j], r, acc);
        }
        out[c] = acc;
    }
}

// -------- init: planarize images, load p, clear done --------
__global__ void k_init(const float* __restrict__ I1,
                       const float* __restrict__ I2,
                       const float* __restrict__ pin) {
    int gid = blockIdx.x*blockDim.x + threadIdx.x;
    if (gid < BB*NPAR) g_p[gid] = pin[gid];
    if (gid < BB) g_done[gid] = 0;
    if (gid < BB*PIX) {
        int b = gid / PIX;
        int r = gid - b*PIX;
#pragma unroll
        for (int c = 0; c < CC; c++) {
            int po = (b*CC + c)*PIX + r;
            g_I1p[po] = I1[gid*3 + c];
            g_I2p[po] = I2[gid*3 + c];
        }
    }
}

// -------- per-iteration reduction: H (21 upper tri) + b (6) --------
__global__ void __launch_bounds__(TBX*TBY) k_iter() {
    int b = blockIdx.y;
    if (g_done[b]) return;
    const float* pb = &g_p[b*NPAR];
    float p0 = pb[0], p1 = pb[1], p2 = pb[2], p3 = pb[3], p4 = pb[4], p5 = pb[5];
    const float* I1b = g_I1p + b*CC*PIX;
    const float* I2b = g_I2p + b*CC*PIX;

    float acc[27];
#pragma unroll
    for (int k = 0; k < 27; k++) acc[k] = 0.0f;

    int rbase = DELTA + blockIdx.x*ROWS1 + threadIdx.y;  // thread-y picks row parity
    for (int hr = 0; hr < ROWS1; hr += TBY) {
        int h = rbase + hr;
        float Y = (float)h;
        for (int w = DELTA + threadIdx.x; w < WW - DELTA; w += TBX) {
            float X = (float)w;
            float xg = fmaf(1.0f + p2, X, fmaf(p3, Y, p0));
            float yg = fmaf(p4, X, fmaf(1.0f + p5, Y, p1));
            float gx = rintf(xg), gy = rintf(yg);
            if (!(gx >= (float)DELTA && gx <= (float)(WW-DELTA) &&
                  gy >= (float)DELTA && gy <= (float)(HH-DELTA))) continue;

            float Iw[3];
            bicubic3(I2b, xg, yg, Iw);

#pragma unroll
            for (int c = 0; c < CC; c++) {
                const float* pc = I1b + c*PIX + h*WW + w;
                float Ix = 0.5f*(__ldg(pc+1)  - __ldg(pc-1));
                float Iy = 0.5f*(__ldg(pc+WW) - __ldg(pc-WW));
                float DI = Iw[c] - __ldg(pc);
                float u  = DI * (1.0f/LAM);
                float wt = rsqrtf(fmaf(u, u, 1.0f));
                float wd = wt * DI;
                float d[6] = {Ix, Iy, Ix*X, Ix*Y, Iy*X, Iy*Y};
                float t[6];
#pragma unroll
                for (int m = 0; m < 6; m++) t[m] = wt * d[m];
                int id = 0;
#pragma unroll
                for (int m = 0; m < 6; m++)
#pragma unroll
                    for (int n = m; n < 6; n++) { acc[id] = fmaf(t[m], d[n], acc[id]); id++; }
#pragma unroll
                for (int m = 0; m < 6; m++) acc[21+m] = fmaf(d[m], wd, acc[21+m]);
            }
        }
    }

    __shared__ float sred[8][27];
    int tid = threadIdx.y*TBX + threadIdx.x;
    int lane = tid & 31, wid = tid >> 5;
#pragma unroll
    for (int k = 0; k < 27; k++) {
        float v = acc[k];
#pragma unroll
        for (int o = 16; o > 0; o >>= 1) v += __shfl_xor_sync(0xffffffffu, v, o);
        if (lane == 0) sred[wid][k] = v;
    }
    __syncthreads();
    if (tid < 27) {
        float s = 0.0f;
#pragma unroll
        for (int wq = 0; wq < (TBX*TBY)/32; wq++) s += sred[wq][tid];
        g_part[(b*NBLK1 + blockIdx.x)*27 + tid] = s;
    }
}

// -------- solve 6x6 + compose update --------
__global__ void k_solve() {
    int b = blockIdx.x;
    if (g_done[b]) return;
    __shared__ double s[27];
    int t = threadIdx.x;
    if (t < 27) {
        double a = 0.0;
        for (int k = 0; k < NBLK1; k++) a += (double)g_part[(b*NBLK1 + k)*27 + t];
        s[t] = a;
    }
    __syncthreads();
    if (t != 0) return;

    double A[6][7];
    int id = 0;
    for (int m = 0; m < 6; m++)
        for (int n = m; n < 6; n++) { A[m][n] = s[id]; A[n][m] = s[id]; id++; }
    for (int m = 0; m < 6; m++) { A[m][m] += 1e-6; A[m][6] = s[21+m]; }

    // Gaussian elimination with partial pivoting
    for (int k = 0; k < 6; k++) {
        int piv = k; double best = fabs(A[k][k]);
        for (int i = k+1; i < 6; i++) { double v = fabs(A[i][k]); if (v > best) { best = v; piv = i; } }
        if (piv != k)
            for (int j = 0; j < 7; j++) { double tmp = A[k][j]; A[k][j] = A[piv][j]; A[piv][j] = tmp; }
        double inv = 1.0 / A[k][k];
        for (int i = k+1; i < 6; i++) {
            double f = A[i][k] * inv;
            for (int j = k; j < 7; j++) A[i][j] -= f * A[k][j];
        }
    }
    double dp[6];
    for (int i = 5; i >= 0; i--) {
        double v = A[i][6];
        for (int j = i+1; j < 6; j++) v -= A[i][j] * dp[j];
        dp[i] = v / A[i][i];
    }
    double nrm2 = 0.0;
    for (int i = 0; i < 6; i++) nrm2 += dp[i]*dp[i];

    // Mn = M(p) @ inv(M(dp))  (both affine, bottom row [0,0,1])
    float* pb = &g_p[b*NPAR];
    double p0 = pb[0], p1 = pb[1], p2 = pb[2], p3 = pb[3], p4 = pb[4], p5 = pb[5];
    double a00 = 1.0+p2, a01 = p3, a02 = p0, a10 = p4, a11 = 1.0+p5, a12 = p1;
    double b00 = 1.0+dp[2], b01 = dp[3], b02 = dp[0], b10 = dp[4], b11 = 1.0+dp[5], b12 = dp[1];
    double det = b00*b11 - b01*b10;
    double c00 =  b11/det, c01 = -b01/det, c10 = -b10/det, c11 =  b00/det;
    double c02 = -(c00*b02 + c01*b12);
    double c12 = -(c10*b02 + c11*b12);
    double n00 = a00*c00 + a01*c10;
    double n01 = a00*c01 + a01*c11;
    double n02 = a00*c02 + a01*c12 + a02;
    double n10 = a10*c00 + a11*c10;
    double n11 = a10*c01 + a11*c11;
    double n12 = a10*c02 + a11*c12 + a12;

    pb[0] = (float)n02; pb[1] = (float)n12;
    pb[2] = (float)(n00 - 1.0); pb[3] = (float)n01;
    pb[4] = (float)n10; pb[5] = (float)(n11 - 1.0);
    if (sqrt(nrm2) < (double)TOLF) g_done[b] = 1;
}

// -------- final pass: Iw, DI outputs + robust error partials --------
__global__ void __launch_bounds__(TBX*TBY) k_final(float* __restrict__ out) {
    int b = blockIdx.y;
    const float* pb = &g_p[b*NPAR];
    float p0 = pb[0], p1 = pb[1], p2 = pb[2], p3 = pb[3], p4 = pb[4], p5 = pb[5];
    const float* I1b = g_I1p + b*CC*PIX;
    const float* I2b = g_I2p + b*CC*PIX;
    float* outDI = out + OUT_DI + (size_t)b*PIX*CC;
    float* outIW = out + OUT_IW + (size_t)b*PIX*CC;

    float rsum = 0.0f, csum = 0.0f;
    int rbase = blockIdx.x*ROWSF + threadIdx.y;
    for (int hr = 0; hr < ROWSF; hr += TBY) {
        int h = rbase + hr;
        float Y = (float)h;
        bool rowok = (h >= DELTA && h < HH-DELTA);
        for (int w = threadIdx.x; w < WW; w += TBX) {
            float X = (float)w;
            float xg = fmaf(1.0f + p2, X, fmaf(p3, Y, p0));
            float yg = fmaf(p4, X, fmaf(1.0f + p5, Y, p1));
            float Iw[3];
            bicubic3(I2b, xg, yg, Iw);
            float gx = rintf(xg), gy = rintf(yg);
            bool wm = (gx >= (float)DELTA && gx <= (float)(WW-DELTA) &&
                       gy >= (float)DELTA && gy <= (float)(HH-DELTA));
            bool m = wm && rowok && (w >= DELTA && w < WW-DELTA);
            int po = h*WW + w;
#pragma unroll
            for (int c = 0; c < CC; c++) {
                float di = m ? (Iw[c] - __ldg(I1b + c*PIX + po)) : 0.0f;
                outDI[po*3 + c] = di;
                outIW[po*3 + c] = Iw[c];
                if (m) {
                    float u = di * (1.0f/LAM);
                    rsum += (2.0f*LAM*LAM) * (sqrtf(fmaf(u, u, 1.0f)) - 1.0f);
                    csum += 1.0f;
                }
            }
        }
    }

    __shared__ float sr[8][2];
    int tid = threadIdx.y*TBX + threadIdx.x;
    int lane = tid & 31, wid = tid >> 5;
    float v0 = rsum, v1r = csum;
#pragma unroll
    for (int o = 16; o > 0; o >>= 1) {
        v0  += __shfl_xor_sync(0xffffffffu, v0,  o);
        v1r += __shfl_xor_sync(0xffffffffu, v1r, o);
    }
    if (lane == 0) { sr[wid][0] = v0; sr[wid][1] = v1r; }
    __syncthreads();
    if (tid < 2) {
        float s = 0.0f;
#pragma unroll
        for (int wq = 0; wq < (TBX*TBY)/32; wq++) s += sr[wq][tid];
        g_fpart[(b*NBLKF + blockIdx.x)*2 + tid] = s;
    }
}

__global__ void k_final2(float* __restrict__ out) {
    int b = blockIdx.x;
    int t = threadIdx.x;
    if (t == 0) {
        double r = 0.0, c = 0.0;
        for (int k = 0; k < NBLKF; k++) {
            r += (double)g_fpart[(b*NBLKF + k)*2 + 0];
            c += (double)g_fpart[(b*NBLKF + k)*2 + 1];
        }
        double cnt = c < 1.0 ? 1.0 : c;
        out[OUT_ERR + b] = (float)(r / cnt);
    }
    if (t < NPAR) out[OUT_P + b*NPAR + t] = g_p[b*NPAR + t];
}

// -------- entry --------
extern "C" void kernel_launch(void* const* d_in, const int* in_sizes, int n_in,
                              void* d_out, int out_size) {
    const float* I1  = (const float*)d_in[0];
    const float* I2  = (const float*)d_in[1];
    const float* pin = (const float*)d_in[2];
    float* out = (float*)d_out;

    k_init<<<(BB*PIX + 255)/256, 256>>>(I1, I2, pin);
    for (int it = 0; it < MAXIT; it++) {
        k_iter<<<dim3(NBLK1, BB), dim3(TBX, TBY)>>>();
        k_solve<<<BB, 32>>>();
    }
    k_final<<<dim3(NBLKF, BB), dim3(TBX, TBY)>>>(out);
    k_final2<<<BB, 32>>>(out);
}